// round 9
// baseline (speedup 1.0000x reference)
#include <cuda_runtime.h>

#define T_STEPS 16384
#define H 361

#define SEG 48
#define SEGP 52
#define NSEG 8
#define HP (NSEG * SEGP)   /* 416 */
#define RPC 48             /* rows per CTA: 8*48=384 >= 361 */
#define CSZ 8
#define PAYB (RPC * 4)     /* 192B bulk payload per (src,dst) pair */
#define TXBYTES (CSZ * PAYB) /* 1536 bytes per consumer per step */

#define KAPPA_F 32.84045313f
#define NORMF   2.2773755f
#define DEG2RAD 0.017453292519943295f

// ---------------- device scratch ----------------
__device__ float g_xw[T_STEPS * H];
__device__ float g_W2T[H * 368];
__device__ float g_A[H];
__device__ float g_C[H];
__device__ float g_hs[T_STEPS * H];

__device__ __forceinline__ unsigned smem_u32(const void* p) {
    return (unsigned)__cvta_generic_to_shared(p);
}
__device__ __forceinline__ unsigned mapa_u32(unsigned addr, unsigned rank) {
    unsigned r;
    asm("mapa.shared::cluster.u32 %0, %1, %2;" : "=r"(r) : "r"(addr), "r"(rank));
    return r;
}

// ---------------- K0: collapse rule projection + biases ----------------
__global__ void k0_prep(const float* __restrict__ w_rule, const float* __restrict__ b_rule,
                        const float* __restrict__ w_ih, const float* __restrict__ b_ih,
                        const float* __restrict__ b_hh) {
    int j = blockIdx.x * blockDim.x + threadIdx.x;
    if (j >= H) return;
    float a = 0.f, c = 0.f;
    const float* wr = w_ih + j * 489;
    for (int k = 0; k < 128; k++) {
        float w = wr[k];
        a = fmaf(w_rule[k], w, a);
        c = fmaf(b_rule[k], w, c);
    }
    g_A[j] = a;
    g_C[j] = c + b_ih[j] + b_hh[j];
}

__global__ void k0_transpose(const float* __restrict__ w_ih) {
    int idx = blockIdx.x * blockDim.x + threadIdx.x;
    if (idx >= H * H) return;
    int j = idx / H;
    int g = idx - j * H;
    g_W2T[g * 368 + j] = w_ih[j * 489 + 128 + g];
}

// ---------------- K1: xw precompute ----------------
#define TT 16
__global__ __launch_bounds__(384) void k1_xw(const float* __restrict__ angle,
                                             const float* __restrict__ rule) {
    __shared__ float sE[TT][H];
    __shared__ float sAng[TT], sRule[TT];
    int tid = threadIdx.x;
    int t0 = blockIdx.x * TT;
    if (tid < TT) {
        sAng[tid]  = angle[t0 + tid] * DEG2RAD;
        sRule[tid] = rule[t0 + tid];
    }
    __syncthreads();
    if (tid < H) {
        float gr = (float)tid * DEG2RAD;
        #pragma unroll
        for (int tt = 0; tt < TT; tt++) {
            float th = gr - sAng[tt];
            sE[tt][tid] = __expf(KAPPA_F * (cosf(th) - 1.0f)) * NORMF;
        }
    }
    __syncthreads();
    if (tid < H) {
        float acc[TT];
        #pragma unroll
        for (int tt = 0; tt < TT; tt++) acc[tt] = 0.f;
        #pragma unroll 2
        for (int g = 0; g < H; g++) {
            float w = g_W2T[g * 368 + tid];
            #pragma unroll
            for (int tt = 0; tt < TT; tt++) acc[tt] = fmaf(sE[tt][g], w, acc[tt]);
        }
        float aj = g_A[tid], cj = g_C[tid];
        #pragma unroll
        for (int tt = 0; tt < TT; tt++)
            g_xw[(t0 + tt) * H + tid] = acc[tt] + fmaf(sRule[tt], aj, cj);
    }
}

// ---------------- K2: sequential RNN, 8-CTA cluster, BULK h broadcast ----------------
// Thread (rr, s): row = rank*48+rr, cols [48s,48s+48) in registers (f32x2).
// Per step: try_wait -> re-arm -> f32x2 dot -> 3 xor shfls -> tanh ->
// stage 48 h values in local smem (STS by row leaders) -> __syncthreads ->
// fence.proxy.async -> lanes 0..7 each issue ONE cp.async.bulk (192B) to one
// destination CTA, fusing data + tx-signal. 8 fabric transactions per CTA
// per step instead of 368 divergent st.async wavefronts.
__global__ void __cluster_dims__(CSZ, 1, 1) __launch_bounds__(384, 1)
k2_rnn(const float* __restrict__ w_hh) {
    __shared__ __align__(16) float hbuf0[HP];
    __shared__ __align__(16) float hbuf1[HP];
    __shared__ __align__(16) float stg0[RPC];
    __shared__ __align__(16) float stg1[RPC];
    __shared__ __align__(8) unsigned long long mbar[2];

    int tid = threadIdx.x;
    unsigned rank;
    asm("mov.u32 %0, %%cluster_ctarank;" : "=r"(rank));
    int s    = tid & 7;
    int rr   = tid >> 3;
    int row  = (int)rank * RPC + rr;
    bool active = (row < H);

    for (int i = tid; i < HP; i += 384) { hbuf0[i] = 0.f; hbuf1[i] = 0.f; }
    if (tid < RPC) { stg0[tid] = 0.f; stg1[tid] = 0.f; }   // pad slots stay 0 forever
    unsigned mb0 = smem_u32(&mbar[0]);
    unsigned mb1 = smem_u32(&mbar[1]);
    if (tid == 0) {
        asm volatile("mbarrier.init.shared.b64 [%0], 1;" :: "r"(mb0) : "memory");
        asm volatile("mbarrier.init.shared.b64 [%0], 1;" :: "r"(mb1) : "memory");
        asm volatile("mbarrier.arrive.expect_tx.shared.b64 _, [%0], %1;"
                     :: "r"(mb0), "r"((unsigned)TXBYTES) : "memory");
        asm volatile("mbarrier.arrive.expect_tx.shared.b64 _, [%0], %1;"
                     :: "r"(mb1), "r"((unsigned)TXBYTES) : "memory");
    }

    // per-thread weight slice packed as f32x2 (zeros where masked)
    unsigned long long wp[SEG / 2];
    #pragma unroll
    for (int i = 0; i < SEG / 2; i++) {
        int c0 = s * SEG + 2 * i;
        int c1 = c0 + 1;
        float a = (active && c0 < H) ? w_hh[row * H + c0] : 0.f;
        float b = (active && c1 < H) ? w_hh[row * H + c1] : 0.f;
        asm("mov.b64 %0, {%1, %2};" : "=l"(wp[i]) : "f"(a), "f"(b));
    }

    // bulk-copy endpoints: lane tid<8 sends this CTA's 192B payload to CTA tid,
    // landing at segment offset rank*SEGP in the destination's hbuf.
    unsigned src0 = smem_u32(stg0);
    unsigned src1 = smem_u32(stg1);
    unsigned bdst0 = 0, bdst1 = 0, brmb0 = 0, brmb1 = 0;
    if (tid < CSZ) {
        unsigned segoff = (unsigned)(rank * SEGP) * 4u;
        bdst0 = mapa_u32(smem_u32(hbuf0) + segoff, (unsigned)tid);
        bdst1 = mapa_u32(smem_u32(hbuf1) + segoff, (unsigned)tid);
        brmb0 = mapa_u32(mb0, (unsigned)tid);
        brmb1 = mapa_u32(mb1, (unsigned)tid);
    }

    float xw_cur = active ? g_xw[row] : 0.f;
    unsigned p0 = 0, p1 = 0;

    __syncthreads();
    asm volatile("barrier.cluster.arrive.aligned;" ::: "memory");
    asm volatile("barrier.cluster.wait.aligned;" ::: "memory");

    for (int t = 0; t < T_STEPS; t++) {
        const float* cur = (t & 1) ? hbuf1 : hbuf0;

        if (t) {
            unsigned mb  = (t & 1) ? mb1 : mb0;
            unsigned par = (t & 1) ? p1 : p0;
            asm volatile(
                "{\n\t.reg .pred P1;\n\t"
                "WAITLP_%=:\n\t"
                "mbarrier.try_wait.parity.acquire.cluster.shared::cta.b64 P1, [%0], %1, 0x989680;\n\t"
                "@!P1 bra WAITLP_%=;\n\t}"
                :: "r"(mb), "r"(par) : "memory");
            if (t & 1) p1 ^= 1; else p0 ^= 1;
            if (tid == 0) {
                asm volatile("mbarrier.arrive.expect_tx.shared.b64 _, [%0], %1;"
                             :: "r"(mb), "r"((unsigned)TXBYTES) : "memory");
            }
        }

        float xw_nxt = 0.f;
        if (active && (t + 1 < T_STEPS)) xw_nxt = __ldg(&g_xw[(t + 1) * H + row]);

        // dot: 12 double2 smem loads + 24 packed f32x2 FMAs, 4 chains
        const double2* h2 = reinterpret_cast<const double2*>(cur + s * SEGP);
        unsigned long long a01 = 0ull, a23 = 0ull, a45 = 0ull, a67 = 0ull;
        #pragma unroll
        for (int i = 0; i < 6; i++) {
            double2 hva = h2[2 * i];
            double2 hvb = h2[2 * i + 1];
            unsigned long long h01 = __double_as_longlong(hva.x);
            unsigned long long h23 = __double_as_longlong(hva.y);
            unsigned long long h45 = __double_as_longlong(hvb.x);
            unsigned long long h67 = __double_as_longlong(hvb.y);
            asm("fma.rn.f32x2 %0, %1, %2, %0;" : "+l"(a01) : "l"(wp[4 * i]),     "l"(h01));
            asm("fma.rn.f32x2 %0, %1, %2, %0;" : "+l"(a23) : "l"(wp[4 * i + 1]), "l"(h23));
            asm("fma.rn.f32x2 %0, %1, %2, %0;" : "+l"(a45) : "l"(wp[4 * i + 2]), "l"(h45));
            asm("fma.rn.f32x2 %0, %1, %2, %0;" : "+l"(a67) : "l"(wp[4 * i + 3]), "l"(h67));
        }
        unsigned long long s0, s1, ssum;
        asm("add.rn.f32x2 %0, %1, %2;" : "=l"(s0) : "l"(a01), "l"(a23));
        asm("add.rn.f32x2 %0, %1, %2;" : "=l"(s1) : "l"(a45), "l"(a67));
        asm("add.rn.f32x2 %0, %1, %2;" : "=l"(ssum) : "l"(s0), "l"(s1));
        unsigned alo, ahi;
        asm("mov.b64 {%0, %1}, %2;" : "=r"(alo), "=r"(ahi) : "l"(ssum));
        float acc = __uint_as_float(alo) + __uint_as_float(ahi);

        acc += __shfl_xor_sync(0xffffffffu, acc, 1);
        acc += __shfl_xor_sync(0xffffffffu, acc, 2);
        acc += __shfl_xor_sync(0xffffffffu, acc, 4);

        // fast tanh in every lane of the row group
        float x = acc + xw_cur;
        float e = __expf(x + x);
        float hval = 1.0f - __fdividef(2.0f, e + 1.0f);

        if (t + 1 < T_STEPS) {
            // stage this CTA's h slice locally (row leaders only)
            float* stg = (t & 1) ? stg0 : stg1;   // staging for buf[(t+1)&1]
            if (active && s == 0) stg[rr] = hval;
            __syncthreads();                       // drain STS
            if (tid < CSZ) {
                asm volatile("fence.proxy.async.shared::cta;" ::: "memory");
                unsigned src = (t & 1) ? src0 : src1;
                unsigned dst = (t & 1) ? bdst0 : bdst1;
                unsigned rmb = (t & 1) ? brmb0 : brmb1;
                asm volatile(
                    "cp.async.bulk.shared::cluster.shared::cta.mbarrier::complete_tx::bytes "
                    "[%0], [%1], %2, [%3];"
                    :: "r"(dst), "r"(src), "r"((unsigned)PAYB), "r"(rmb) : "memory");
            }
        }
        if (active && s == 0) g_hs[t * H + row] = hval;
        xw_cur = xw_nxt;
    }
    asm volatile("barrier.cluster.arrive.aligned;" ::: "memory");
    asm volatile("barrier.cluster.wait.aligned;" ::: "memory");
}

// ---------------- K3: outcome_pre + hs copy-out ----------------
__global__ void k3_outcome(const float* __restrict__ w_fc, const float* __restrict__ b_fc,
                           float* __restrict__ pre) {
    __shared__ float swfc[H];
    for (int i = threadIdx.x; i < H; i += blockDim.x) swfc[i] = w_fc[i];
    __syncthreads();
    int lane = threadIdx.x & 31;
    int wid  = threadIdx.x >> 5;
    int wpb  = blockDim.x >> 5;
    float bf = b_fc[0];
    for (int t = blockIdx.x * wpb + wid; t < T_STEPS; t += gridDim.x * wpb) {
        const float* hrow = g_hs + t * H;
        float acc = 0.f;
        for (int i = lane; i < H; i += 32) acc = fmaf(hrow[i], swfc[i], acc);
        #pragma unroll
        for (int o = 16; o > 0; o >>= 1) acc += __shfl_xor_sync(0xffffffffu, acc, o);
        if (lane == 0) pre[t] = acc + bf;
    }
}

__global__ void k3_copy(float* __restrict__ dst) {
    const float4* src = reinterpret_cast<const float4*>(g_hs);
    float4* d = reinterpret_cast<float4*>(dst);
    int n4 = T_STEPS * H / 4;
    for (int i = blockIdx.x * blockDim.x + threadIdx.x; i < n4; i += gridDim.x * blockDim.x)
        d[i] = src[i];
}

// ---------------- launch ----------------
extern "C" void kernel_launch(void* const* d_in, const int* in_sizes, int n_in,
                              void* d_out, int out_size) {
    const float* angle  = (const float*)d_in[0];
    const float* rule   = (const float*)d_in[1];
    const float* w_rule = (const float*)d_in[2];
    const float* b_rule = (const float*)d_in[3];
    const float* w_ih   = (const float*)d_in[4];
    const float* w_hh   = (const float*)d_in[5];
    const float* b_ih   = (const float*)d_in[6];
    const float* b_hh   = (const float*)d_in[7];
    const float* w_fc   = (const float*)d_in[8];
    const float* b_fc   = (const float*)d_in[9];
    float* out = (float*)d_out;

    k0_prep<<<(H + 255) / 256, 256>>>(w_rule, b_rule, w_ih, b_ih, b_hh);
    k0_transpose<<<(H * H + 255) / 256, 256>>>(w_ih);
    k1_xw<<<T_STEPS / TT, 384>>>(angle, rule);
    k2_rnn<<<CSZ, 384>>>(w_hh);

    float* pre = nullptr;
    float* hs_dst = nullptr;
    if (out_size == T_STEPS * (H + 1)) { pre = out; hs_dst = out + T_STEPS; }
    else if (out_size == T_STEPS * H)  { hs_dst = out; }
    else if (out_size == T_STEPS)      { pre = out; }
    else {
        pre = out;
        if (out_size >= T_STEPS * (H + 1)) hs_dst = out + (out_size - T_STEPS * H);
    }
    if (hs_dst) k3_copy<<<1024, 256>>>(hs_dst);
    if (pre)    k3_outcome<<<256, 256>>>(w_fc, b_fc, pre);
}

// round 10
// speedup vs baseline: 1.1612x; 1.1612x over previous
#include <cuda_runtime.h>

#define T_STEPS 16384
#define H 361

#define CSZ 12             /* cluster CTAs == sources == segments */
#define RPC 32             /* rows per CTA (lane l <-> row rank*32+l); 12*32=384>=361 */
#define SEGC 32            /* columns per segment */
#define HB 384             /* h buffer floats */
#define NTHR 384           /* 12 warps: warp s consumes source s */
#define TXB 128            /* 32 lanes x 4B per (source, consumer, step) */
#define PSTR 33            /* psum row stride (conflict-free) */

#define KAPPA_F 32.84045313f
#define NORMF   2.2773755f
#define DEG2RAD 0.017453292519943295f

// ---------------- device scratch ----------------
__device__ float g_xw[T_STEPS * H];
__device__ float g_W2T[H * 368];
__device__ float g_A[H];
__device__ float g_C[H];
__device__ float g_hs[T_STEPS * H];

__device__ __forceinline__ unsigned smem_u32(const void* p) {
    return (unsigned)__cvta_generic_to_shared(p);
}
__device__ __forceinline__ unsigned mapa_u32(unsigned addr, unsigned rank) {
    unsigned r;
    asm("mapa.shared::cluster.u32 %0, %1, %2;" : "=r"(r) : "r"(addr), "r"(rank));
    return r;
}

// ---------------- K0: collapse rule projection + biases ----------------
__global__ void k0_prep(const float* __restrict__ w_rule, const float* __restrict__ b_rule,
                        const float* __restrict__ w_ih, const float* __restrict__ b_ih,
                        const float* __restrict__ b_hh) {
    int j = blockIdx.x * blockDim.x + threadIdx.x;
    if (j >= H) return;
    float a = 0.f, c = 0.f;
    const float* wr = w_ih + j * 489;
    for (int k = 0; k < 128; k++) {
        float w = wr[k];
        a = fmaf(w_rule[k], w, a);
        c = fmaf(b_rule[k], w, c);
    }
    g_A[j] = a;
    g_C[j] = c + b_ih[j] + b_hh[j];
}

__global__ void k0_transpose(const float* __restrict__ w_ih) {
    int idx = blockIdx.x * blockDim.x + threadIdx.x;
    if (idx >= H * H) return;
    int j = idx / H;
    int g = idx - j * H;
    g_W2T[g * 368 + j] = w_ih[j * 489 + 128 + g];
}

// ---------------- K1: xw precompute ----------------
#define TT 16
__global__ __launch_bounds__(384) void k1_xw(const float* __restrict__ angle,
                                             const float* __restrict__ rule) {
    __shared__ float sE[TT][H];
    __shared__ float sAng[TT], sRule[TT];
    int tid = threadIdx.x;
    int t0 = blockIdx.x * TT;
    if (tid < TT) {
        sAng[tid]  = angle[t0 + tid] * DEG2RAD;
        sRule[tid] = rule[t0 + tid];
    }
    __syncthreads();
    if (tid < H) {
        float gr = (float)tid * DEG2RAD;
        #pragma unroll
        for (int tt = 0; tt < TT; tt++) {
            float th = gr - sAng[tt];
            sE[tt][tid] = __expf(KAPPA_F * (cosf(th) - 1.0f)) * NORMF;
        }
    }
    __syncthreads();
    if (tid < H) {
        float acc[TT];
        #pragma unroll
        for (int tt = 0; tt < TT; tt++) acc[tt] = 0.f;
        #pragma unroll 2
        for (int g = 0; g < H; g++) {
            float w = g_W2T[g * 368 + tid];
            #pragma unroll
            for (int tt = 0; tt < TT; tt++) acc[tt] = fmaf(sE[tt][g], w, acc[tt]);
        }
        float aj = g_A[tid], cj = g_C[tid];
        #pragma unroll
        for (int tt = 0; tt < TT; tt++)
            g_xw[(t0 + tt) * H + tid] = acc[tt] + fmaf(sRule[tt], aj, cj);
    }
}

// ---------------- K2: warp-per-source RNN, 12-CTA cluster ----------------
// Warp s (lane l): partial for row rank*32+l over cols [32s, 32s+32), gated by
// per-source mbarrier[buf][s] (tx=128B). STS partial -> BAR -> warp 0 sums 12
// partials per row, tanh, coalesced g_hs STG, then 12 single-dest coalesced
// st.async (data + tx-signal) delivering h_{t+1} to every CTA.
__global__ void __launch_bounds__(NTHR, 1)
k2_rnn(const float* __restrict__ w_hh) {
    __shared__ __align__(16) float hbuf0[HB];
    __shared__ __align__(16) float hbuf1[HB];
    __shared__ float psum[CSZ * PSTR];
    __shared__ __align__(8) unsigned long long mbar[2][CSZ];

    int tid  = threadIdx.x;
    int lane = tid & 31;
    int s    = tid >> 5;          // warp id == source/segment id
    unsigned rank;
    asm("mov.u32 %0, %%cluster_ctarank;" : "=r"(rank));
    int grow = (int)rank * RPC + lane;   // the row this lane serves
    bool rowok = (grow < H);

    for (int i = tid; i < HB; i += NTHR) { hbuf0[i] = 0.f; hbuf1[i] = 0.f; }
    if (tid == 0) {
        for (int b = 0; b < 2; b++)
            for (int k = 0; k < CSZ; k++) {
                unsigned mb = smem_u32(&mbar[b][k]);
                asm volatile("mbarrier.init.shared.b64 [%0], 1;" :: "r"(mb) : "memory");
                asm volatile("mbarrier.arrive.expect_tx.shared.b64 _, [%0], %1;"
                             :: "r"(mb), "r"((unsigned)TXB) : "memory");
            }
    }

    // weights: lane l of warp s holds W[grow, 32s..32s+32) as 16 f32x2
    unsigned long long wp[SEGC / 2];
    #pragma unroll
    for (int i = 0; i < SEGC / 2; i++) {
        int c0 = s * SEGC + 2 * i;
        int c1 = c0 + 1;
        float a = (rowok && c0 < H) ? w_hh[grow * H + c0] : 0.f;
        float b = (rowok && c1 < H) ? w_hh[grow * H + c1] : 0.f;
        asm("mov.b64 %0, {%1, %2};" : "=l"(wp[i]) : "f"(a), "f"(b));
    }

    unsigned mbA = smem_u32(&mbar[0][s]);   // my wait barriers
    unsigned mbB = smem_u32(&mbar[1][s]);
    // send bases (warp 0): my segment lands at float offset rank*32 in consumers
    unsigned sb0 = smem_u32(hbuf0) + (unsigned)(rank * RPC + lane) * 4u;
    unsigned sb1 = smem_u32(hbuf1) + (unsigned)(rank * RPC + lane) * 4u;
    unsigned smb0 = smem_u32(&mbar[0][rank]);
    unsigned smb1 = smem_u32(&mbar[1][rank]);

    float xw_cur = (s == 0 && rowok) ? g_xw[grow] : 0.f;
    unsigned pA = 0, pB = 0;

    __syncthreads();
    asm volatile("barrier.cluster.arrive.aligned;" ::: "memory");
    asm volatile("barrier.cluster.wait.aligned;" ::: "memory");

    for (int t = 0; t < T_STEPS; t++) {
        const float* cur = (t & 1) ? hbuf1 : hbuf0;

        if (t) {
            unsigned mb  = (t & 1) ? mbB : mbA;
            unsigned par = (t & 1) ? pB : pA;
            if (lane == 0) {
                asm volatile(
                    "{\n\t.reg .pred P1;\n\t"
                    "WAITLP_%=:\n\t"
                    "mbarrier.try_wait.parity.acquire.cluster.shared::cta.b64 P1, [%0], %1, 0x989680;\n\t"
                    "@!P1 bra WAITLP_%=;\n\t}"
                    :: "r"(mb), "r"(par) : "memory");
                // re-arm for t+2 (complete_tx-before-expect_tx is legal)
                asm volatile("mbarrier.arrive.expect_tx.shared.b64 _, [%0], %1;"
                             :: "r"(mb), "r"((unsigned)TXB) : "memory");
            }
            __syncwarp();
            if (t & 1) pB ^= 1; else pA ^= 1;
        }

        // segment dot: 8 broadcast double2 LDS + 16 f32x2 FMAs (2 chains)
        const double2* h2 = reinterpret_cast<const double2*>(cur + s * SEGC);
        unsigned long long a01 = 0ull, a23 = 0ull;
        #pragma unroll
        for (int i = 0; i < 8; i++) {
            double2 hv = h2[i];
            unsigned long long hlo = __double_as_longlong(hv.x);
            unsigned long long hhi = __double_as_longlong(hv.y);
            asm("fma.rn.f32x2 %0, %1, %2, %0;" : "+l"(a01) : "l"(wp[2 * i]),     "l"(hlo));
            asm("fma.rn.f32x2 %0, %1, %2, %0;" : "+l"(a23) : "l"(wp[2 * i + 1]), "l"(hhi));
        }
        unsigned long long ssum;
        asm("add.rn.f32x2 %0, %1, %2;" : "=l"(ssum) : "l"(a01), "l"(a23));
        unsigned alo, ahi;
        asm("mov.b64 {%0, %1}, %2;" : "=r"(alo), "=r"(ahi) : "l"(ssum));
        psum[s * PSTR + lane] = __uint_as_float(alo) + __uint_as_float(ahi);

        __syncthreads();   // all 12 partials staged; also fences buf reads

        if (s == 0) {
            float xw_nxt = 0.f;
            if (rowok && (t + 1 < T_STEPS)) xw_nxt = __ldg(&g_xw[(t + 1) * H + grow]);

            float v = psum[lane];
            #pragma unroll
            for (int k = 1; k < CSZ; k++) v += psum[k * PSTR + lane];

            float x = v + xw_cur;
            float e = __expf(x + x);
            float hval = 1.0f - __fdividef(2.0f, e + 1.0f);   // pad rows -> exactly 0

            if (rowok) g_hs[t * H + grow] = hval;             // coalesced STG

            if (t + 1 < T_STEPS) {
                unsigned r_  = __float_as_uint(hval);
                unsigned src = (t & 1) ? sb0 : sb1;           // target buf (t+1)&1
                unsigned smb = (t & 1) ? smb0 : smb1;
                #pragma unroll
                for (int k = 0; k < CSZ; k++) {
                    unsigned d = mapa_u32(src, (unsigned)k);
                    unsigned m = mapa_u32(smb, (unsigned)k);
                    asm volatile(
                        "st.async.shared::cluster.mbarrier::complete_tx::bytes.u32 [%0], %1, [%2];"
                        :: "r"(d), "r"(r_), "r"(m) : "memory");
                }
            }
            xw_cur = xw_nxt;
        }
    }
    asm volatile("barrier.cluster.arrive.aligned;" ::: "memory");
    asm volatile("barrier.cluster.wait.aligned;" ::: "memory");
}

// ---------------- K3: outcome_pre + hs copy-out ----------------
__global__ void k3_outcome(const float* __restrict__ w_fc, const float* __restrict__ b_fc,
                           float* __restrict__ pre) {
    __shared__ float swfc[H];
    for (int i = threadIdx.x; i < H; i += blockDim.x) swfc[i] = w_fc[i];
    __syncthreads();
    int lane = threadIdx.x & 31;
    int wid  = threadIdx.x >> 5;
    int wpb  = blockDim.x >> 5;
    float bf = b_fc[0];
    for (int t = blockIdx.x * wpb + wid; t < T_STEPS; t += gridDim.x * wpb) {
        const float* hrow = g_hs + t * H;
        float acc = 0.f;
        for (int i = lane; i < H; i += 32) acc = fmaf(hrow[i], swfc[i], acc);
        #pragma unroll
        for (int o = 16; o > 0; o >>= 1) acc += __shfl_xor_sync(0xffffffffu, acc, o);
        if (lane == 0) pre[t] = acc + bf;
    }
}

__global__ void k3_copy(float* __restrict__ dst) {
    const float4* src = reinterpret_cast<const float4*>(g_hs);
    float4* d = reinterpret_cast<float4*>(dst);
    int n4 = T_STEPS * H / 4;
    for (int i = blockIdx.x * blockDim.x + threadIdx.x; i < n4; i += gridDim.x * blockDim.x)
        d[i] = src[i];
}

// ---------------- launch ----------------
extern "C" void kernel_launch(void* const* d_in, const int* in_sizes, int n_in,
                              void* d_out, int out_size) {
    const float* angle  = (const float*)d_in[0];
    const float* rule   = (const float*)d_in[1];
    const float* w_rule = (const float*)d_in[2];
    const float* b_rule = (const float*)d_in[3];
    const float* w_ih   = (const float*)d_in[4];
    const float* w_hh   = (const float*)d_in[5];
    const float* b_ih   = (const float*)d_in[6];
    const float* b_hh   = (const float*)d_in[7];
    const float* w_fc   = (const float*)d_in[8];
    const float* b_fc   = (const float*)d_in[9];
    float* out = (float*)d_out;

    k0_prep<<<(H + 255) / 256, 256>>>(w_rule, b_rule, w_ih, b_ih, b_hh);
    k0_transpose<<<(H * H + 255) / 256, 256>>>(w_ih);
    k1_xw<<<T_STEPS / TT, 384>>>(angle, rule);

    // 12-CTA nonportable cluster launch
    cudaFuncSetAttribute(k2_rnn, cudaFuncAttributeNonPortableClusterSizeAllowed, 1);
    {
        cudaLaunchConfig_t cfg = {};
        cfg.gridDim  = dim3(CSZ, 1, 1);
        cfg.blockDim = dim3(NTHR, 1, 1);
        cfg.dynamicSmemBytes = 0;
        cfg.stream = 0;
        cudaLaunchAttribute attrs[1];
        attrs[0].id = cudaLaunchAttributeClusterDimension;
        attrs[0].val.clusterDim.x = CSZ;
        attrs[0].val.clusterDim.y = 1;
        attrs[0].val.clusterDim.z = 1;
        cfg.attrs = attrs;
        cfg.numAttrs = 1;
        cudaLaunchKernelEx(&cfg, k2_rnn, w_hh);
    }

    float* pre = nullptr;
    float* hs_dst = nullptr;
    if (out_size == T_STEPS * (H + 1)) { pre = out; hs_dst = out + T_STEPS; }
    else if (out_size == T_STEPS * H)  { hs_dst = out; }
    else if (out_size == T_STEPS)      { pre = out; }
    else {
        pre = out;
        if (out_size >= T_STEPS * (H + 1)) hs_dst = out + (out_size - T_STEPS * H);
    }
    if (hs_dst) k3_copy<<<1024, 256>>>(hs_dst);
    if (pre)    k3_outcome<<<256, 256>>>(w_fc, b_fc, pre);
}

// round 11
// speedup vs baseline: 1.8376x; 1.5825x over previous
#include <cuda_runtime.h>

#define T_STEPS 16384
#define H 361

#define CSZ 12             /* cluster CTAs == sources == segments */
#define RPC 32             /* rows per CTA (lane l <-> row rank*32+l) */
#define SEGC 32            /* columns per segment */
#define HB 384             /* h buffer floats */
#define NTHR 384           /* 12 warps: warp s consumes source s, sends to CTA s */
#define TXB 128            /* 32 lanes x 4B per (source, consumer, step) */
#define PSTR 33            /* psum row stride (conflict-free) */

#define KAPPA_F 32.84045313f
#define NORMF   2.2773755f
#define DEG2RAD 0.017453292519943295f

// ---------------- device scratch ----------------
__device__ float g_xw[T_STEPS * H];
__device__ float g_W2T[H * 368];
__device__ float g_A[H];
__device__ float g_C[H];
__device__ float g_hs[T_STEPS * H];

__device__ __forceinline__ unsigned smem_u32(const void* p) {
    return (unsigned)__cvta_generic_to_shared(p);
}
__device__ __forceinline__ unsigned mapa_u32(unsigned addr, unsigned rank) {
    unsigned r;
    asm("mapa.shared::cluster.u32 %0, %1, %2;" : "=r"(r) : "r"(addr), "r"(rank));
    return r;
}

// ---------------- K0: collapse rule projection + biases ----------------
__global__ void k0_prep(const float* __restrict__ w_rule, const float* __restrict__ b_rule,
                        const float* __restrict__ w_ih, const float* __restrict__ b_ih,
                        const float* __restrict__ b_hh) {
    int j = blockIdx.x * blockDim.x + threadIdx.x;
    if (j >= H) return;
    float a = 0.f, c = 0.f;
    const float* wr = w_ih + j * 489;
    for (int k = 0; k < 128; k++) {
        float w = wr[k];
        a = fmaf(w_rule[k], w, a);
        c = fmaf(b_rule[k], w, c);
    }
    g_A[j] = a;
    g_C[j] = c + b_ih[j] + b_hh[j];
}

__global__ void k0_transpose(const float* __restrict__ w_ih) {
    int idx = blockIdx.x * blockDim.x + threadIdx.x;
    if (idx >= H * H) return;
    int j = idx / H;
    int g = idx - j * H;
    g_W2T[g * 368 + j] = w_ih[j * 489 + 128 + g];
}

// ---------------- K1: xw precompute ----------------
#define TT 16
__global__ __launch_bounds__(384) void k1_xw(const float* __restrict__ angle,
                                             const float* __restrict__ rule) {
    __shared__ float sE[TT][H];
    __shared__ float sAng[TT], sRule[TT];
    int tid = threadIdx.x;
    int t0 = blockIdx.x * TT;
    if (tid < TT) {
        sAng[tid]  = angle[t0 + tid] * DEG2RAD;
        sRule[tid] = rule[t0 + tid];
    }
    __syncthreads();
    if (tid < H) {
        float gr = (float)tid * DEG2RAD;
        #pragma unroll
        for (int tt = 0; tt < TT; tt++) {
            float th = gr - sAng[tt];
            sE[tt][tid] = __expf(KAPPA_F * (cosf(th) - 1.0f)) * NORMF;
        }
    }
    __syncthreads();
    if (tid < H) {
        float acc[TT];
        #pragma unroll
        for (int tt = 0; tt < TT; tt++) acc[tt] = 0.f;
        #pragma unroll 2
        for (int g = 0; g < H; g++) {
            float w = g_W2T[g * 368 + tid];
            #pragma unroll
            for (int tt = 0; tt < TT; tt++) acc[tt] = fmaf(sE[tt][g], w, acc[tt]);
        }
        float aj = g_A[tid], cj = g_C[tid];
        #pragma unroll
        for (int tt = 0; tt < TT; tt++)
            g_xw[(t0 + tt) * H + tid] = acc[tt] + fmaf(sRule[tt], aj, cj);
    }
}

// ---------------- K2: warp-per-source RNN, 12-CTA cluster, distributed sends ----------------
// Warp s (lane l): partial for row rank*32+l over cols [32s,32s+32), gated by
// per-source mbarrier[buf][s] (tx=128B). All lanes try_wait (warp-synchronous,
// no syncwarp); lane0 re-arms. STS partial (warp0 folds xw in) -> BAR -> EVERY
// warp redundantly sums 12 partials + tanh; warp s issues ONE coalesced 128B
// st.async to CTA s (data + tx-signal). Warp 1 stores g_hs.
__global__ void __launch_bounds__(NTHR, 1)
k2_rnn(const float* __restrict__ w_hh) {
    __shared__ __align__(16) float hbuf0[HB];
    __shared__ __align__(16) float hbuf1[HB];
    __shared__ float psum[CSZ * PSTR];
    __shared__ __align__(8) unsigned long long mbar[2][CSZ];

    int tid  = threadIdx.x;
    int lane = tid & 31;
    int s    = tid >> 5;          // warp id == source id == send-dest CTA id
    unsigned rank;
    asm("mov.u32 %0, %%cluster_ctarank;" : "=r"(rank));
    int grow = (int)rank * RPC + lane;   // the row this lane serves
    bool rowok = (grow < H);

    for (int i = tid; i < HB; i += NTHR) { hbuf0[i] = 0.f; hbuf1[i] = 0.f; }
    if (tid == 0) {
        for (int b = 0; b < 2; b++)
            for (int k = 0; k < CSZ; k++) {
                unsigned mb = smem_u32(&mbar[b][k]);
                asm volatile("mbarrier.init.shared.b64 [%0], 1;" :: "r"(mb) : "memory");
                asm volatile("mbarrier.arrive.expect_tx.shared.b64 _, [%0], %1;"
                             :: "r"(mb), "r"((unsigned)TXB) : "memory");
            }
    }

    // weights: lane l of warp s holds W[grow, 32s..32s+32) as 16 f32x2
    unsigned long long wp[SEGC / 2];
    #pragma unroll
    for (int i = 0; i < SEGC / 2; i++) {
        int c0 = s * SEGC + 2 * i;
        int c1 = c0 + 1;
        float a = (rowok && c0 < H) ? w_hh[grow * H + c0] : 0.f;
        float b = (rowok && c1 < H) ? w_hh[grow * H + c1] : 0.f;
        asm("mov.b64 %0, {%1, %2};" : "=l"(wp[i]) : "f"(a), "f"(b));
    }

    unsigned mbA = smem_u32(&mbar[0][s]);   // my wait barriers (source s)
    unsigned mbB = smem_u32(&mbar[1][s]);
    // my send endpoint: warp s delivers this CTA's 32 h values to CTA s,
    // landing at float offset rank*32, signaling CTA s's barrier[.][rank]
    unsigned sd0 = 0, sd1 = 0, sm0 = 0, sm1 = 0;
    {
        unsigned off = (unsigned)(rank * RPC + lane) * 4u;
        sd0 = mapa_u32(smem_u32(hbuf0) + off, (unsigned)s);
        sd1 = mapa_u32(smem_u32(hbuf1) + off, (unsigned)s);
        sm0 = mapa_u32(smem_u32(&mbar[0][rank]), (unsigned)s);
        sm1 = mapa_u32(smem_u32(&mbar[1][rank]), (unsigned)s);
    }

    float xw_cur = (s == 0 && rowok) ? g_xw[grow] : 0.f;
    unsigned pA = 0, pB = 0;

    __syncthreads();
    asm volatile("barrier.cluster.arrive.aligned;" ::: "memory");
    asm volatile("barrier.cluster.wait.aligned;" ::: "memory");

    for (int t = 0; t < T_STEPS; t++) {
        const float* cur = (t & 1) ? hbuf1 : hbuf0;

        if (t) {
            unsigned mb  = (t & 1) ? mbB : mbA;
            unsigned par = (t & 1) ? pB : pA;
            // all lanes wait (warp-synchronous poll); no syncwarp needed
            asm volatile(
                "{\n\t.reg .pred P1;\n\t"
                "WAITLP_%=:\n\t"
                "mbarrier.try_wait.parity.acquire.cluster.shared::cta.b64 P1, [%0], %1, 0x989680;\n\t"
                "@!P1 bra WAITLP_%=;\n\t}"
                :: "r"(mb), "r"(par) : "memory");
            if (lane == 0) {   // re-arm for t+2 (early complete_tx is legal)
                asm volatile("mbarrier.arrive.expect_tx.shared.b64 _, [%0], %1;"
                             :: "r"(mb), "r"((unsigned)TXB) : "memory");
            }
            if (t & 1) pB ^= 1; else pA ^= 1;
        }

        // segment dot: 8 broadcast double2 LDS + 16 f32x2 FMAs (2 chains)
        const double2* h2 = reinterpret_cast<const double2*>(cur + s * SEGC);
        unsigned long long a01 = 0ull, a23 = 0ull;
        #pragma unroll
        for (int i = 0; i < 8; i++) {
            double2 hv = h2[i];
            unsigned long long hlo = __double_as_longlong(hv.x);
            unsigned long long hhi = __double_as_longlong(hv.y);
            asm("fma.rn.f32x2 %0, %1, %2, %0;" : "+l"(a01) : "l"(wp[2 * i]),     "l"(hlo));
            asm("fma.rn.f32x2 %0, %1, %2, %0;" : "+l"(a23) : "l"(wp[2 * i + 1]), "l"(hhi));
        }
        unsigned long long ssum;
        asm("add.rn.f32x2 %0, %1, %2;" : "=l"(ssum) : "l"(a01), "l"(a23));
        unsigned alo, ahi;
        asm("mov.b64 {%0, %1}, %2;" : "=r"(alo), "=r"(ahi) : "l"(ssum));
        float part = __uint_as_float(alo) + __uint_as_float(ahi);
        if (s == 0) part += xw_cur;            // fold input drive into partial 0
        psum[s * PSTR + lane] = part;

        // prefetch next xw while waiting at the barrier (warp 0 only)
        float xw_nxt = 0.f;
        if (s == 0 && rowok && (t + 1 < T_STEPS)) xw_nxt = __ldg(&g_xw[(t + 1) * H + grow]);

        __syncthreads();   // all 12 partials staged; also fences buf reads

        // every warp redundantly: full sum + tanh (parallel across SMSPs)
        float v = psum[lane];
        #pragma unroll
        for (int k = 1; k < CSZ; k++) v += psum[k * PSTR + lane];
        float e = __expf(v + v);
        float hval = 1.0f - __fdividef(2.0f, e + 1.0f);   // pad rows -> exactly 0

        if (s == 1 && rowok) g_hs[t * H + grow] = hval;   // coalesced STG, warp 1

        if (t + 1 < T_STEPS) {
            // warp s: ONE coalesced 128B st.async to CTA s (buf (t+1)&1)
            unsigned d = (t & 1) ? sd0 : sd1;
            unsigned m = (t & 1) ? sm0 : sm1;
            asm volatile(
                "st.async.shared::cluster.mbarrier::complete_tx::bytes.u32 [%0], %1, [%2];"
                :: "r"(d), "r"(__float_as_uint(hval)), "r"(m) : "memory");
        }
        xw_cur = xw_nxt;
    }
    asm volatile("barrier.cluster.arrive.aligned;" ::: "memory");
    asm volatile("barrier.cluster.wait.aligned;" ::: "memory");
}

// ---------------- K3: outcome_pre + hs copy-out ----------------
__global__ void k3_outcome(const float* __restrict__ w_fc, const float* __restrict__ b_fc,
                           float* __restrict__ pre) {
    __shared__ float swfc[H];
    for (int i = threadIdx.x; i < H; i += blockDim.x) swfc[i] = w_fc[i];
    __syncthreads();
    int lane = threadIdx.x & 31;
    int wid  = threadIdx.x >> 5;
    int wpb  = blockDim.x >> 5;
    float bf = b_fc[0];
    for (int t = blockIdx.x * wpb + wid; t < T_STEPS; t += gridDim.x * wpb) {
        const float* hrow = g_hs + t * H;
        float acc = 0.f;
        for (int i = lane; i < H; i += 32) acc = fmaf(hrow[i], swfc[i], acc);
        #pragma unroll
        for (int o = 16; o > 0; o >>= 1) acc += __shfl_xor_sync(0xffffffffu, acc, o);
        if (lane == 0) pre[t] = acc + bf;
    }
}

__global__ void k3_copy(float* __restrict__ dst) {
    const float4* src = reinterpret_cast<const float4*>(g_hs);
    float4* d = reinterpret_cast<float4*>(dst);
    int n4 = T_STEPS * H / 4;
    for (int i = blockIdx.x * blockDim.x + threadIdx.x; i < n4; i += gridDim.x * blockDim.x)
        d[i] = src[i];
}

// ---------------- launch ----------------
extern "C" void kernel_launch(void* const* d_in, const int* in_sizes, int n_in,
                              void* d_out, int out_size) {
    const float* angle  = (const float*)d_in[0];
    const float* rule   = (const float*)d_in[1];
    const float* w_rule = (const float*)d_in[2];
    const float* b_rule = (const float*)d_in[3];
    const float* w_ih   = (const float*)d_in[4];
    const float* w_hh   = (const float*)d_in[5];
    const float* b_ih   = (const float*)d_in[6];
    const float* b_hh   = (const float*)d_in[7];
    const float* w_fc   = (const float*)d_in[8];
    const float* b_fc   = (const float*)d_in[9];
    float* out = (float*)d_out;

    k0_prep<<<(H + 255) / 256, 256>>>(w_rule, b_rule, w_ih, b_ih, b_hh);
    k0_transpose<<<(H * H + 255) / 256, 256>>>(w_ih);
    k1_xw<<<T_STEPS / TT, 384>>>(angle, rule);

    // 12-CTA nonportable cluster launch
    cudaFuncSetAttribute(k2_rnn, cudaFuncAttributeNonPortableClusterSizeAllowed, 1);
    {
        cudaLaunchConfig_t cfg = {};
        cfg.gridDim  = dim3(CSZ, 1, 1);
        cfg.blockDim = dim3(NTHR, 1, 1);
        cfg.dynamicSmemBytes = 0;
        cfg.stream = 0;
        cudaLaunchAttribute attrs[1];
        attrs[0].id = cudaLaunchAttributeClusterDimension;
        attrs[0].val.clusterDim.x = CSZ;
        attrs[0].val.clusterDim.y = 1;
        attrs[0].val.clusterDim.z = 1;
        cfg.attrs = attrs;
        cfg.numAttrs = 1;
        cudaLaunchKernelEx(&cfg, k2_rnn, w_hh);
    }

    float* pre = nullptr;
    float* hs_dst = nullptr;
    if (out_size == T_STEPS * (H + 1)) { pre = out; hs_dst = out + T_STEPS; }
    else if (out_size == T_STEPS * H)  { hs_dst = out; }
    else if (out_size == T_STEPS)      { pre = out; }
    else {
        pre = out;
        if (out_size >= T_STEPS * (H + 1)) hs_dst = out + (out_size - T_STEPS * H);
    }
    if (hs_dst) k3_copy<<<1024, 256>>>(hs_dst);
    if (pre)    k3_outcome<<<256, 256>>>(w_fc, b_fc, pre);
}

// round 12
// speedup vs baseline: 1.9346x; 1.0528x over previous
#include <cuda_runtime.h>

#define T_STEPS 16384
#define H 361

#define CSZ 12             /* cluster CTAs == sources == segments */
#define RPC 32             /* rows per CTA (lane l <-> row rank*32+l) */
#define SEGC 32            /* columns per segment */
#define HB 384             /* h buffer floats */
#define NTHR 384           /* 12 warps: warp s consumes source s, sends to CTA s */
#define TXB 128            /* 32 lanes x 4B per (source, consumer, step) */
#define PSTR 33            /* psum row stride (conflict-free) */

#define KAPPA_F 32.84045313f
#define NORMF   2.2773755f
#define DEG2RAD 0.017453292519943295f
#define SC2LOG2E 2.885390081777927f   /* 2*log2(e): pre-scale so sum feeds ex2 */

// ---------------- device scratch ----------------
__device__ float g_xw[T_STEPS * H];     // stores 2*log2(e) * xw
__device__ float g_W2T[H * 368];
__device__ float g_A[H];
__device__ float g_C[H];
__device__ float g_hs[T_STEPS * H];

__device__ __forceinline__ unsigned smem_u32(const void* p) {
    return (unsigned)__cvta_generic_to_shared(p);
}
__device__ __forceinline__ unsigned mapa_u32(unsigned addr, unsigned rank) {
    unsigned r;
    asm("mapa.shared::cluster.u32 %0, %1, %2;" : "=r"(r) : "r"(addr), "r"(rank));
    return r;
}

// ---------------- K0: collapse rule projection + biases ----------------
__global__ void k0_prep(const float* __restrict__ w_rule, const float* __restrict__ b_rule,
                        const float* __restrict__ w_ih, const float* __restrict__ b_ih,
                        const float* __restrict__ b_hh) {
    int j = blockIdx.x * blockDim.x + threadIdx.x;
    if (j >= H) return;
    float a = 0.f, c = 0.f;
    const float* wr = w_ih + j * 489;
    for (int k = 0; k < 128; k++) {
        float w = wr[k];
        a = fmaf(w_rule[k], w, a);
        c = fmaf(b_rule[k], w, c);
    }
    g_A[j] = a;
    g_C[j] = c + b_ih[j] + b_hh[j];
}

__global__ void k0_transpose(const float* __restrict__ w_ih) {
    int idx = blockIdx.x * blockDim.x + threadIdx.x;
    if (idx >= H * H) return;
    int j = idx / H;
    int g = idx - j * H;
    g_W2T[g * 368 + j] = w_ih[j * 489 + 128 + g];
}

// ---------------- K1: xw precompute (output pre-scaled by 2*log2e) ----------------
#define TT 16
__global__ __launch_bounds__(384) void k1_xw(const float* __restrict__ angle,
                                             const float* __restrict__ rule) {
    __shared__ float sE[TT][H];
    __shared__ float sAng[TT], sRule[TT];
    int tid = threadIdx.x;
    int t0 = blockIdx.x * TT;
    if (tid < TT) {
        sAng[tid]  = angle[t0 + tid] * DEG2RAD;
        sRule[tid] = rule[t0 + tid];
    }
    __syncthreads();
    if (tid < H) {
        float gr = (float)tid * DEG2RAD;
        #pragma unroll
        for (int tt = 0; tt < TT; tt++) {
            float th = gr - sAng[tt];
            sE[tt][tid] = __expf(KAPPA_F * (cosf(th) - 1.0f)) * NORMF;
        }
    }
    __syncthreads();
    if (tid < H) {
        float acc[TT];
        #pragma unroll
        for (int tt = 0; tt < TT; tt++) acc[tt] = 0.f;
        #pragma unroll 2
        for (int g = 0; g < H; g++) {
            float w = g_W2T[g * 368 + tid];
            #pragma unroll
            for (int tt = 0; tt < TT; tt++) acc[tt] = fmaf(sE[tt][g], w, acc[tt]);
        }
        float aj = g_A[tid], cj = g_C[tid];
        #pragma unroll
        for (int tt = 0; tt < TT; tt++)
            g_xw[(t0 + tt) * H + tid] = (acc[tt] + fmaf(sRule[tt], aj, cj)) * SC2LOG2E;
    }
}

// ---------------- K2: warp-per-source RNN, 12-CTA cluster, distributed sends ----------------
// R12 deltas vs R11: weights/xw pre-scaled by 2*log2e so the reduced sum feeds
// ex2 directly; depth-4 tree sum of the 12 partials; mbarrier re-arm moved
// after the send (off the wait->dot critical path).
__global__ void __launch_bounds__(NTHR, 1)
k2_rnn(const float* __restrict__ w_hh) {
    __shared__ __align__(16) float hbuf0[HB];
    __shared__ __align__(16) float hbuf1[HB];
    __shared__ float psum[CSZ * PSTR];
    __shared__ __align__(8) unsigned long long mbar[2][CSZ];

    int tid  = threadIdx.x;
    int lane = tid & 31;
    int s    = tid >> 5;          // warp id == source id == send-dest CTA id
    unsigned rank;
    asm("mov.u32 %0, %%cluster_ctarank;" : "=r"(rank));
    int grow = (int)rank * RPC + lane;   // the row this lane serves
    bool rowok = (grow < H);

    for (int i = tid; i < HB; i += NTHR) { hbuf0[i] = 0.f; hbuf1[i] = 0.f; }
    if (tid == 0) {
        for (int b = 0; b < 2; b++)
            for (int k = 0; k < CSZ; k++) {
                unsigned mb = smem_u32(&mbar[b][k]);
                asm volatile("mbarrier.init.shared.b64 [%0], 1;" :: "r"(mb) : "memory");
                asm volatile("mbarrier.arrive.expect_tx.shared.b64 _, [%0], %1;"
                             :: "r"(mb), "r"((unsigned)TXB) : "memory");
            }
    }

    // weights: lane l of warp s holds 2log2e * W[grow, 32s..32s+32) as 16 f32x2
    unsigned long long wp[SEGC / 2];
    #pragma unroll
    for (int i = 0; i < SEGC / 2; i++) {
        int c0 = s * SEGC + 2 * i;
        int c1 = c0 + 1;
        float a = (rowok && c0 < H) ? w_hh[grow * H + c0] * SC2LOG2E : 0.f;
        float b = (rowok && c1 < H) ? w_hh[grow * H + c1] * SC2LOG2E : 0.f;
        asm("mov.b64 %0, {%1, %2};" : "=l"(wp[i]) : "f"(a), "f"(b));
    }

    unsigned mbA = smem_u32(&mbar[0][s]);   // my wait barriers (source s)
    unsigned mbB = smem_u32(&mbar[1][s]);
    // my send endpoint: warp s delivers this CTA's 32 h values to CTA s
    unsigned sd0 = 0, sd1 = 0, sm0 = 0, sm1 = 0;
    {
        unsigned off = (unsigned)(rank * RPC + lane) * 4u;
        sd0 = mapa_u32(smem_u32(hbuf0) + off, (unsigned)s);
        sd1 = mapa_u32(smem_u32(hbuf1) + off, (unsigned)s);
        sm0 = mapa_u32(smem_u32(&mbar[0][rank]), (unsigned)s);
        sm1 = mapa_u32(smem_u32(&mbar[1][rank]), (unsigned)s);
    }

    float xw_cur = (s == 0 && rowok) ? g_xw[grow] : 0.f;
    unsigned pA = 0, pB = 0;

    __syncthreads();
    asm volatile("barrier.cluster.arrive.aligned;" ::: "memory");
    asm volatile("barrier.cluster.wait.aligned;" ::: "memory");

    for (int t = 0; t < T_STEPS; t++) {
        const float* cur = (t & 1) ? hbuf1 : hbuf0;
        unsigned mb = (t & 1) ? mbB : mbA;

        if (t) {
            unsigned par = (t & 1) ? pB : pA;
            // all lanes wait (warp-synchronous poll)
            asm volatile(
                "{\n\t.reg .pred P1;\n\t"
                "WAITLP_%=:\n\t"
                "mbarrier.try_wait.parity.acquire.cluster.shared::cta.b64 P1, [%0], %1, 0x989680;\n\t"
                "@!P1 bra WAITLP_%=;\n\t}"
                :: "r"(mb), "r"(par) : "memory");
            if (t & 1) pB ^= 1; else pA ^= 1;
        }

        // segment dot: 8 broadcast 16B LDS + 16 f32x2 FMAs (2 chains)
        const double2* h2 = reinterpret_cast<const double2*>(cur + s * SEGC);
        unsigned long long a01 = 0ull, a23 = 0ull;
        #pragma unroll
        for (int i = 0; i < 8; i++) {
            double2 hv = h2[i];
            unsigned long long hlo = __double_as_longlong(hv.x);
            unsigned long long hhi = __double_as_longlong(hv.y);
            asm("fma.rn.f32x2 %0, %1, %2, %0;" : "+l"(a01) : "l"(wp[2 * i]),     "l"(hlo));
            asm("fma.rn.f32x2 %0, %1, %2, %0;" : "+l"(a23) : "l"(wp[2 * i + 1]), "l"(hhi));
        }
        unsigned long long ssum;
        asm("add.rn.f32x2 %0, %1, %2;" : "=l"(ssum) : "l"(a01), "l"(a23));
        unsigned alo, ahi;
        asm("mov.b64 {%0, %1}, %2;" : "=r"(alo), "=r"(ahi) : "l"(ssum));
        float part = __uint_as_float(alo) + __uint_as_float(ahi);
        if (s == 0) part += xw_cur;            // fold (pre-scaled) input drive
        psum[s * PSTR + lane] = part;

        // prefetch next xw while others finish (warp 0 only)
        float xw_nxt = 0.f;
        if (s == 0 && rowok && (t + 1 < T_STEPS)) xw_nxt = __ldg(&g_xw[(t + 1) * H + grow]);

        __syncthreads();   // all 12 partials staged; also fences buf reads

        // every warp redundantly: depth-4 tree sum + tanh (parallel across SMSPs)
        float p0  = psum[lane],             p1  = psum[PSTR + lane];
        float p2  = psum[2 * PSTR + lane],  p3  = psum[3 * PSTR + lane];
        float p4  = psum[4 * PSTR + lane],  p5  = psum[5 * PSTR + lane];
        float p6  = psum[6 * PSTR + lane],  p7  = psum[7 * PSTR + lane];
        float p8  = psum[8 * PSTR + lane],  p9  = psum[9 * PSTR + lane];
        float p10 = psum[10 * PSTR + lane], p11 = psum[11 * PSTR + lane];
        float q0 = p0 + p1,  q1 = p2 + p3,  q2 = p4 + p5;
        float q3 = p6 + p7,  q4 = p8 + p9,  q5 = p10 + p11;
        float r0 = q0 + q1,  r1 = q2 + q3,  r2 = q4 + q5;
        float v  = (r0 + r1) + r2;          // = 2*log2e*(W h + xw)

        float e;
        asm("ex2.approx.f32 %0, %1;" : "=f"(e) : "f"(v));   // e^{2x}
        float hval = 1.0f - __fdividef(2.0f, e + 1.0f);     // tanh(x); pads -> 0

        if (s == 1 && rowok) g_hs[t * H + grow] = hval;     // coalesced STG, warp 1

        if (t + 1 < T_STEPS) {
            // warp s: ONE coalesced 128B st.async to CTA s (buf (t+1)&1)
            unsigned d = (t & 1) ? sd0 : sd1;
            unsigned m = (t & 1) ? sm0 : sm1;
            asm volatile(
                "st.async.shared::cluster.mbarrier::complete_tx::bytes.u32 [%0], %1, [%2];"
                :: "r"(d), "r"(__float_as_uint(hval)), "r"(m) : "memory");
        }
        // re-arm the barrier consumed this step, for step t+2 (off critical path;
        // early complete_tx is legal — pending arrive gates phase completion)
        if (t && lane == 0) {
            asm volatile("mbarrier.arrive.expect_tx.shared.b64 _, [%0], %1;"
                         :: "r"(mb), "r"((unsigned)TXB) : "memory");
        }
        xw_cur = xw_nxt;
    }
    asm volatile("barrier.cluster.arrive.aligned;" ::: "memory");
    asm volatile("barrier.cluster.wait.aligned;" ::: "memory");
}

// ---------------- K3: outcome_pre + hs copy-out ----------------
__global__ void k3_outcome(const float* __restrict__ w_fc, const float* __restrict__ b_fc,
                           float* __restrict__ pre) {
    __shared__ float swfc[H];
    for (int i = threadIdx.x; i < H; i += blockDim.x) swfc[i] = w_fc[i];
    __syncthreads();
    int lane = threadIdx.x & 31;
    int wid  = threadIdx.x >> 5;
    int wpb  = blockDim.x >> 5;
    float bf = b_fc[0];
    for (int t = blockIdx.x * wpb + wid; t < T_STEPS; t += gridDim.x * wpb) {
        const float* hrow = g_hs + t * H;
        float acc = 0.f;
        for (int i = lane; i < H; i += 32) acc = fmaf(hrow[i], swfc[i], acc);
        #pragma unroll
        for (int o = 16; o > 0; o >>= 1) acc += __shfl_xor_sync(0xffffffffu, acc, o);
        if (lane == 0) pre[t] = acc + bf;
    }
}

__global__ void k3_copy(float* __restrict__ dst) {
    const float4* src = reinterpret_cast<const float4*>(g_hs);
    float4* d = reinterpret_cast<float4*>(dst);
    int n4 = T_STEPS * H / 4;
    for (int i = blockIdx.x * blockDim.x + threadIdx.x; i < n4; i += gridDim.x * blockDim.x)
        d[i] = src[i];
}

// ---------------- launch ----------------
extern "C" void kernel_launch(void* const* d_in, const int* in_sizes, int n_in,
                              void* d_out, int out_size) {
    const float* angle  = (const float*)d_in[0];
    const float* rule   = (const float*)d_in[1];
    const float* w_rule = (const float*)d_in[2];
    const float* b_rule = (const float*)d_in[3];
    const float* w_ih   = (const float*)d_in[4];
    const float* w_hh   = (const float*)d_in[5];
    const float* b_ih   = (const float*)d_in[6];
    const float* b_hh   = (const float*)d_in[7];
    const float* w_fc   = (const float*)d_in[8];
    const float* b_fc   = (const float*)d_in[9];
    float* out = (float*)d_out;

    k0_prep<<<(H + 255) / 256, 256>>>(w_rule, b_rule, w_ih, b_ih, b_hh);
    k0_transpose<<<(H * H + 255) / 256, 256>>>(w_ih);
    k1_xw<<<T_STEPS / TT, 384>>>(angle, rule);

    // 12-CTA nonportable cluster launch
    cudaFuncSetAttribute(k2_rnn, cudaFuncAttributeNonPortableClusterSizeAllowed, 1);
    {
        cudaLaunchConfig_t cfg = {};
        cfg.gridDim  = dim3(CSZ, 1, 1);
        cfg.blockDim = dim3(NTHR, 1, 1);
        cfg.dynamicSmemBytes = 0;
        cfg.stream = 0;
        cudaLaunchAttribute attrs[1];
        attrs[0].id = cudaLaunchAttributeClusterDimension;
        attrs[0].val.clusterDim.x = CSZ;
        attrs[0].val.clusterDim.y = 1;
        attrs[0].val.clusterDim.z = 1;
        cfg.attrs = attrs;
        cfg.numAttrs = 1;
        cudaLaunchKernelEx(&cfg, k2_rnn, w_hh);
    }

    float* pre = nullptr;
    float* hs_dst = nullptr;
    if (out_size == T_STEPS * (H + 1)) { pre = out; hs_dst = out + T_STEPS; }
    else if (out_size == T_STEPS * H)  { hs_dst = out; }
    else if (out_size == T_STEPS)      { pre = out; }
    else {
        pre = out;
        if (out_size >= T_STEPS * (H + 1)) hs_dst = out + (out_size - T_STEPS * H);
    }
    if (hs_dst) k3_copy<<<1024, 256>>>(hs_dst);
    if (pre)    k3_outcome<<<256, 256>>>(w_fc, b_fc, pre);
}